// round 8
// baseline (speedup 1.0000x reference)
#include <cuda_runtime.h>
#include <cuda_fp16.h>
#include <stdint.h>

#define KG_MAX 200000
#define B_MAX  20000
#define E_MAX  640000
#define IN_DIM 256
#define OUT_DIM 128

// ---------------- device scratch ----------------
__device__ int   g_is64;
__device__ __align__(16) float g_vL[IN_DIM];
__device__ __align__(16) float g_vR[IN_DIM];
__device__ float g_cLR;
__device__ float g_dR[KG_MAX];
__device__ float g_sL[B_MAX];
__device__ int   g_cnt[B_MAX];
__device__ int   g_cur[B_MAX];
__device__ int   g_off[B_MAX + 1];
__device__ int   g_csr[E_MAX];
__device__ __align__(128) __half g_enth[(size_t)KG_MAX * IN_DIM];
__device__ __align__(128) __half g_Yh[(size_t)B_MAX * IN_DIM];
__device__ __align__(16) unsigned g_Wfrag[16 * 16 * 32 * 2];

__device__ __forceinline__ int ld_row(const void* p, int e, int is64) {
    return is64 ? (int)((const long long*)p)[e] : ((const int*)p)[e];
}
__device__ __forceinline__ int ld_col(const void* p, int E, int e, int is64) {
    return is64 ? (int)((const long long*)p)[(long long)E + e]
                : ((const int*)p)[E + e];
}

// 256-bit L2-policy loads (sm_103: evict hints require .v8.b32)
__device__ __forceinline__ void ldg256_keep(const __half* p, uint4& lo, uint4& hi) {
    asm volatile(
        "ld.global.nc.L2::evict_last.v8.b32 {%0,%1,%2,%3,%4,%5,%6,%7}, [%8];"
        : "=r"(lo.x), "=r"(lo.y), "=r"(lo.z), "=r"(lo.w),
          "=r"(hi.x), "=r"(hi.y), "=r"(hi.z), "=r"(hi.w)
        : "l"(p));
}
__device__ __forceinline__ void ldg256_stream(const float* p, float4& x0, float4& x1) {
    unsigned r0, r1, r2, r3, r4, r5, r6, r7;
    asm volatile(
        "ld.global.nc.L2::evict_first.v8.b32 {%0,%1,%2,%3,%4,%5,%6,%7}, [%8];"
        : "=r"(r0), "=r"(r1), "=r"(r2), "=r"(r3),
          "=r"(r4), "=r"(r5), "=r"(r6), "=r"(r7)
        : "l"(p));
    x0.x = __uint_as_float(r0); x0.y = __uint_as_float(r1);
    x0.z = __uint_as_float(r2); x0.w = __uint_as_float(r3);
    x1.x = __uint_as_float(r4); x1.y = __uint_as_float(r5);
    x1.z = __uint_as_float(r6); x1.w = __uint_as_float(r7);
}

// ---------------- k_prep ----------------
__global__ void k_prep(const void* __restrict__ bids,
                       const float* __restrict__ W,
                       const float* __restrict__ bias,
                       const float* __restrict__ wa,
                       int B) {
    int t = threadIdx.x;  // 256
    __shared__ int s_nz;
    if (t == 0) s_nz = 0;
    __syncthreads();
    const unsigned int* u = (const unsigned int*)bids;
    if (u[2 * t + 1] != 0u) atomicOr(&s_nz, 1);
    __syncthreads();
    if (t == 0) g_is64 = s_nz ? 0 : 1;

    float vl = 0.f, vr = 0.f;
#pragma unroll 4
    for (int n = 0; n < OUT_DIM; n++) {
        float w = W[n * IN_DIM + t];
        vl = fmaf(w, wa[n], vl);
        vr = fmaf(w, wa[OUT_DIM + n], vr);
    }
    g_vL[t] = vl;
    g_vR[t] = vr;

    __shared__ float sr[256];
    sr[t] = (t < OUT_DIM) ? bias[t] * (wa[t] + wa[t + OUT_DIM]) : 0.f;
    __syncthreads();
    for (int off = 128; off > 0; off >>= 1) {
        if (t < off) sr[t] += sr[t + off];
        __syncthreads();
    }
    if (t == 0) g_cLR = sr[0];

    // pack W into mma.m16n8k16 B-fragment order (fp16)
    for (int f = t; f < 16 * 16 * 32 * 2; f += 256) {
        int q = f & 1;
        int lane = (f >> 1) & 31;
        int nf = (f >> 6) & 15;
        int ks = f >> 10;
        int n = nf * 8 + (lane >> 2);
        int k = ks * 16 + (lane & 3) * 2 + (q ? 8 : 0);
        __half2 h = __floats2half2_rn(W[n * IN_DIM + k], W[n * IN_DIM + k + 1]);
        g_Wfrag[f] = *(unsigned*)&h;
    }
    for (int i = t; i < B; i += 256) { g_cnt[i] = 0; g_cur[i] = 0; }
}

// ---------------- k_fused: dR + fp16 convert + sL (stream A) --------
__global__ void __launch_bounds__(256) k_fused(
        const float* __restrict__ ent, const void* __restrict__ bids,
        int KG, int B, int nbdr) {
    int bid = blockIdx.x;
    int t = threadIdx.x, w = t >> 5, lane = t & 31;
    if (bid < nbdr) {
        int v = bid * 8 + w;
        if (v < KG) {
            const float* x = ent + (size_t)v * IN_DIM + lane * 8;
            float4 x0, x1;
            ldg256_stream(x, x0, x1);
            float4 r0 = *(const float4*)&g_vR[lane * 8];
            float4 r1 = *(const float4*)&g_vR[lane * 8 + 4];
            float d = x0.x * r0.x + x0.y * r0.y + x0.z * r0.z + x0.w * r0.w
                    + x1.x * r1.x + x1.y * r1.y + x1.z * r1.z + x1.w * r1.w;
#pragma unroll
            for (int o = 16; o > 0; o >>= 1)
                d += __shfl_xor_sync(0xffffffffu, d, o);
            if (lane == 0) g_dR[v] = d;
            __half2 h0 = __floats2half2_rn(x0.x, x0.y);
            __half2 h1 = __floats2half2_rn(x0.z, x0.w);
            __half2 h2 = __floats2half2_rn(x1.x, x1.y);
            __half2 h3 = __floats2half2_rn(x1.z, x1.w);
            uint4 q;
            q.x = *(unsigned int*)&h0; q.y = *(unsigned int*)&h1;
            q.z = *(unsigned int*)&h2; q.w = *(unsigned int*)&h3;
            ((uint4*)g_enth)[(size_t)v * 32 + lane] = q;
        }
    } else {
        int r = (bid - nbdr) * 8 + w;
        if (r < B) {
            long long gi = g_is64 ? ((const long long*)bids)[r]
                                  : (long long)((const int*)bids)[r];
            const float* x = ent + gi * (long long)IN_DIM + lane * 8;
            float4 x0 = *(const float4*)x;
            float4 x1 = *(const float4*)(x + 4);
            float4 l0 = *(const float4*)&g_vL[lane * 8];
            float4 l1 = *(const float4*)&g_vL[lane * 8 + 4];
            float d = x0.x * l0.x + x0.y * l0.y + x0.z * l0.z + x0.w * l0.w
                    + x1.x * l1.x + x1.y * l1.y + x1.z * l1.z + x1.w * l1.w;
#pragma unroll
            for (int o = 16; o > 0; o >>= 1)
                d += __shfl_xor_sync(0xffffffffu, d, o);
            if (lane == 0) g_sL[r] = d + g_cLR;
        }
    }
}

// ---------------- CSR chain (stream B) ----------------
__global__ void k_hist(const void* __restrict__ ei, int E) {
    int e = blockIdx.x * blockDim.x + threadIdx.x;
    if (e >= E) return;
    int r = ld_row(ei, e, g_is64);
    atomicAdd(&g_cnt[r], 1);
}

__global__ void k_scan(int B) {
    __shared__ int s[1024];
    int t = threadIdx.x;
    int CH = (B + 1023) >> 10;
    int lo = t * CH, hi = min(lo + CH, B);
    int sum = 0;
    for (int i = lo; i < hi; i++) sum += g_cnt[i];
    s[t] = sum;
    __syncthreads();
    for (int off = 1; off < 1024; off <<= 1) {
        int v = (t >= off) ? s[t - off] : 0;
        __syncthreads();
        s[t] += v;
        __syncthreads();
    }
    int run = (t == 0) ? 0 : s[t - 1];
    for (int i = lo; i < hi; i++) { g_off[i] = run; run += g_cnt[i]; }
    if (t == 1023) g_off[B] = s[1023];
}

__global__ void k_scatter(const void* __restrict__ ei, int E) {
    int e = blockIdx.x * blockDim.x + threadIdx.x;
    if (e >= E) return;
    int r = ld_row(ei, e, g_is64);
    int pos = atomicAdd(&g_cur[r], 1);
    g_csr[g_off[r] + pos] = e;
}

// ---------------- warp-register bitonic sort of 64 ints (2/lane) -----------
__device__ __forceinline__ void bitonic64(int& v0, int& v1, int lane) {
#pragma unroll
    for (int k = 2; k <= 32; k <<= 1) {
#pragma unroll
        for (int j = k >> 1; j > 0; j >>= 1) {
            bool low = ((lane & j) == 0);
            int x0 = __shfl_xor_sync(0xffffffffu, v0, j);
            bool asc0 = ((lane & k) == 0);
            v0 = (asc0 == low) ? min(v0, x0) : max(v0, x0);
            int x1 = __shfl_xor_sync(0xffffffffu, v1, j);
            bool asc1 = (k == 32) ? false : asc0;
            v1 = (asc1 == low) ? min(v1, x1) : max(v1, x1);
        }
    }
    { int mn = min(v0, v1), mx = max(v0, v1); v0 = mn; v1 = mx; }
#pragma unroll
    for (int j = 16; j > 0; j >>= 1) {
        bool low = ((lane & j) == 0);
        int x0 = __shfl_xor_sync(0xffffffffu, v0, j);
        v0 = low ? min(v0, x0) : max(v0, x0);
        int x1 = __shfl_xor_sync(0xffffffffu, v1, j);
        v1 = low ? min(v1, x1) : max(v1, x1);
    }
}

// ---------------- k_agg: 256-bit gather, 2 edges per warp step -------------
// Edge row = 512B = 16 lanes x 32B. Half-warp A (lanes 0-15) takes even edge
// indices, half B (16-31) odd. Each lane owns 16 embed columns. Final merge:
// A[j] += shfl_down(A[j], 16) in fixed order -> deterministic.
__global__ void __launch_bounds__(256) k_agg(const void* __restrict__ ei,
                                             int E, int B) {
    __shared__ int   s_e[8][128];
    __shared__ float s_a[8][128];
    int t = threadIdx.x, w = t >> 5, lane = t & 31;
    int r = blockIdx.x * 8 + w;
    if (r >= B) return;
    int is64 = g_is64;
    int off0 = g_off[r];
    int deg = g_off[r + 1] - off0;
    float base = g_sL[r];

    int half = lane >> 4, hl = lane & 15;
    const __half* ehp = g_enth + (size_t)hl * 16;  // lane's 16-col slice
    float A[16];
#pragma unroll
    for (int j = 0; j < 16; j++) A[j] = 0.f;
    float asum = 0.f;

#define ACC16(lo, hi, a) do { \
        float2 f; \
        f = __half22float2(*(__half2*)&(lo).x); \
        A[0] = fmaf((a), f.x, A[0]);  A[1] = fmaf((a), f.y, A[1]); \
        f = __half22float2(*(__half2*)&(lo).y); \
        A[2] = fmaf((a), f.x, A[2]);  A[3] = fmaf((a), f.y, A[3]); \
        f = __half22float2(*(__half2*)&(lo).z); \
        A[4] = fmaf((a), f.x, A[4]);  A[5] = fmaf((a), f.y, A[5]); \
        f = __half22float2(*(__half2*)&(lo).w); \
        A[6] = fmaf((a), f.x, A[6]);  A[7] = fmaf((a), f.y, A[7]); \
        f = __half22float2(*(__half2*)&(hi).x); \
        A[8] = fmaf((a), f.x, A[8]);  A[9] = fmaf((a), f.y, A[9]); \
        f = __half22float2(*(__half2*)&(hi).y); \
        A[10] = fmaf((a), f.x, A[10]); A[11] = fmaf((a), f.y, A[11]); \
        f = __half22float2(*(__half2*)&(hi).z); \
        A[12] = fmaf((a), f.x, A[12]); A[13] = fmaf((a), f.y, A[13]); \
        f = __half22float2(*(__half2*)&(hi).w); \
        A[14] = fmaf((a), f.x, A[14]); A[15] = fmaf((a), f.y, A[15]); \
    } while (0)

    // lane handles edge i+half in each pair; 4 pairs staged per iteration
#define GATHER256() do { \
        int i = 0; \
        for (; i + 8 <= deg; i += 8) { \
            int e0 = i + half, e1 = i + 2 + half; \
            int e2 = i + 4 + half, e3 = i + 6 + half; \
            int c0 = s_e[w][e0], c1 = s_e[w][e1]; \
            int c2 = s_e[w][e2], c3 = s_e[w][e3]; \
            uint4 l0, h0, l1, h1, l2, h2, l3, h3; \
            ldg256_keep(ehp + (size_t)c0 * IN_DIM, l0, h0); \
            ldg256_keep(ehp + (size_t)c1 * IN_DIM, l1, h1); \
            ldg256_keep(ehp + (size_t)c2 * IN_DIM, l2, h2); \
            ldg256_keep(ehp + (size_t)c3 * IN_DIM, l3, h3); \
            float a0 = s_a[w][e0], a1 = s_a[w][e1]; \
            float a2 = s_a[w][e2], a3 = s_a[w][e3]; \
            ACC16(l0, h0, a0); ACC16(l1, h1, a1); \
            ACC16(l2, h2, a2); ACC16(l3, h3, a3); \
        } \
        for (; i < deg; i += 2) { \
            int e = i + half; \
            int c = 0; float a = 0.f; \
            if (e < deg) { c = s_e[w][e]; a = s_a[w][e]; } \
            uint4 lo, hi; \
            ldg256_keep(ehp + (size_t)c * IN_DIM, lo, hi); \
            ACC16(lo, hi, a); \
        } \
    } while (0)

    if (deg <= 64) {
        int v0 = (lane < deg) ? g_csr[off0 + lane] : 0x7fffffff;
        int v1 = (32 + lane < deg) ? g_csr[off0 + 32 + lane] : 0x7fffffff;
        bitonic64(v0, v1, lane);
        float ap = 0.f;
        if (lane < deg) {
            int c = ld_col(ei, E, v0, is64);
            float s = base + g_dR[c];
            float v = s >= 0.f ? s : 0.2f * s;
            float a = __expf(-v);
            s_e[w][lane] = c; s_a[w][lane] = a;
            ap += a;
        }
        if (32 + lane < deg) {
            int c = ld_col(ei, E, v1, is64);
            float s = base + g_dR[c];
            float v = s >= 0.f ? s : 0.2f * s;
            float a = __expf(-v);
            s_e[w][32 + lane] = c; s_a[w][32 + lane] = a;
            ap += a;
        }
#pragma unroll
        for (int o = 16; o > 0; o >>= 1)
            ap += __shfl_xor_sync(0xffffffffu, ap, o);
        asum = ap;
        __syncwarp();
        GATHER256();
    } else if (deg <= 128) {
        int P = 1;
        while (P < deg) P <<= 1;
        for (int i = lane; i < P; i += 32)
            s_e[w][i] = (i < deg) ? g_csr[off0 + i] : 0x7fffffff;
        __syncwarp();
        for (int k = 2; k <= P; k <<= 1) {
            for (int j = k >> 1; j > 0; j >>= 1) {
                for (int i = lane; i < P; i += 32) {
                    int ixj = i ^ j;
                    if (ixj > i) {
                        int a = s_e[w][i], c = s_e[w][ixj];
                        bool up = ((i & k) == 0);
                        if ((a > c) == up) { s_e[w][i] = c; s_e[w][ixj] = a; }
                    }
                }
                __syncwarp();
            }
        }
        float ap = 0.f;
        for (int i = lane; i < deg; i += 32) {
            int e = s_e[w][i];
            int c = ld_col(ei, E, e, is64);
            float s = base + g_dR[c];
            float v = s >= 0.f ? s : 0.2f * s;
            float a = __expf(-v);
            s_e[w][i] = c;
            s_a[w][i] = a;
            ap += a;
        }
#pragma unroll
        for (int o = 16; o > 0; o >>= 1)
            ap += __shfl_xor_sync(0xffffffffu, ap, o);
        asum = ap;
        __syncwarp();
        GATHER256();
    } else {
        // deterministic fallback: serial increasing edge-id; half B idle (a=0)
        int last = -1;
        for (int rk = 0; rk < deg; rk++) {
            int m = 0x7fffffff;
            for (int i = lane; i < deg; i += 32) {
                int ec = g_csr[off0 + i];
                if (ec > last && ec < m) m = ec;
            }
#pragma unroll
            for (int o = 16; o > 0; o >>= 1)
                m = min(m, __shfl_xor_sync(0xffffffffu, m, o));
            int c = ld_col(ei, E, m, is64);
            float s = base + g_dR[c];
            float v = s >= 0.f ? s : 0.2f * s;
            float a = __expf(-v);
            asum += a;
            float am = (half == 0) ? a : 0.f;
            int cm = (half == 0) ? c : 0;
            uint4 lo, hi;
            ldg256_keep(ehp + (size_t)cm * IN_DIM, lo, hi);
            ACC16(lo, hi, am);
            last = m;
        }
    }
#undef GATHER256
#undef ACC16

    // merge half B into half A (fixed order), then write fp16 Y
#pragma unroll
    for (int j = 0; j < 16; j++) {
        float o = __shfl_down_sync(0xffffffffu, A[j], 16);
        A[j] += o;
    }
    if (half == 0) {
        float inv = 1.0f / asum;
        __half2 h[8];
#pragma unroll
        for (int j = 0; j < 8; j++)
            h[j] = __floats2half2_rn(A[2 * j] * inv, A[2 * j + 1] * inv);
        uint4 q0, q1;
        q0.x = *(unsigned*)&h[0]; q0.y = *(unsigned*)&h[1];
        q0.z = *(unsigned*)&h[2]; q0.w = *(unsigned*)&h[3];
        q1.x = *(unsigned*)&h[4]; q1.y = *(unsigned*)&h[5];
        q1.z = *(unsigned*)&h[6]; q1.w = *(unsigned*)&h[7];
        uint4* yp = ((uint4*)g_Yh) + (size_t)r * 32 + hl * 2;
        yp[0] = q0;
        yp[1] = q1;
    }
}

// ---------------- k_gemm: HMMA m16n8k16 ----------------
__global__ void __launch_bounds__(256) k_gemm(const float* __restrict__ bias,
                                              const float* __restrict__ prelu,
                                              float* __restrict__ out, int M) {
    int tid = threadIdx.x;
    int wid = tid >> 5, lane = tid & 31;
    int gid = lane >> 2, tig = lane & 3;
    int mbase = blockIdx.x * 128 + wid * 16;
    int r0 = mbase + gid, r1 = r0 + 8;
    bool p0 = r0 < M, p1 = r1 < M;

    float acc[16][4];
#pragma unroll
    for (int nf = 0; nf < 16; nf++)
#pragma unroll
        for (int j = 0; j < 4; j++) acc[nf][j] = 0.f;

    const __half* Yh = g_Yh;
    const uint2* Wf = (const uint2*)g_Wfrag;

    for (int ks = 0; ks < 16; ks++) {
        int k0 = ks * 16 + tig * 2;
        unsigned a0 = p0 ? *(const unsigned*)&Yh[(size_t)r0 * IN_DIM + k0] : 0u;
        unsigned a1 = p1 ? *(const unsigned*)&Yh[(size_t)r1 * IN_DIM + k0] : 0u;
        unsigned a2 = p0 ? *(const unsigned*)&Yh[(size_t)r0 * IN_DIM + k0 + 8] : 0u;
        unsigned a3 = p1 ? *(const unsigned*)&Yh[(size_t)r1 * IN_DIM + k0 + 8] : 0u;
#pragma unroll
        for (int nf = 0; nf < 16; nf++) {
            uint2 bb = __ldg(&Wf[(ks * 16 + nf) * 32 + lane]);
            asm volatile(
                "mma.sync.aligned.m16n8k16.row.col.f32.f16.f16.f32 "
                "{%0,%1,%2,%3}, {%4,%5,%6,%7}, {%8,%9}, {%0,%1,%2,%3};"
                : "+f"(acc[nf][0]), "+f"(acc[nf][1]),
                  "+f"(acc[nf][2]), "+f"(acc[nf][3])
                : "r"(a0), "r"(a1), "r"(a2), "r"(a3),
                  "r"(bb.x), "r"(bb.y));
        }
    }

    float pw = prelu[0];
#pragma unroll
    for (int nf = 0; nf < 16; nf++) {
        int n0 = nf * 8 + tig * 2;
        float bv0 = __ldg(&bias[n0]), bv1 = __ldg(&bias[n0 + 1]);
        if (p0) {
            float v0 = acc[nf][0] + bv0, v1 = acc[nf][1] + bv1;
            float2 o;
            o.x = v0 >= 0.f ? v0 : pw * v0;
            o.y = v1 >= 0.f ? v1 : pw * v1;
            *(float2*)&out[(size_t)r0 * OUT_DIM + n0] = o;
        }
        if (p1) {
            float v2 = acc[nf][2] + bv0, v3 = acc[nf][3] + bv1;
            float2 o;
            o.x = v2 >= 0.f ? v2 : pw * v2;
            o.y = v3 >= 0.f ? v3 : pw * v3;
            *(float2*)&out[(size_t)r1 * OUT_DIM + n0] = o;
        }
    }
}

// ---------------- launch ----------------
extern "C" void kernel_launch(void* const* d_in, const int* in_sizes, int n_in,
                              void* d_out, int out_size) {
    const float* ent  = (const float*)d_in[0];
    const void*  bids = d_in[1];
    const void*  ei   = d_in[2];
    const float* W    = (const float*)d_in[3];
    const float* bias = (const float*)d_in[4];
    const float* wa   = (const float*)d_in[5];
    const float* pw   = (const float*)d_in[6];

    int KG = in_sizes[0] / IN_DIM;
    int B  = in_sizes[1];
    int E  = in_sizes[2] / 2;
    if (KG > KG_MAX) KG = KG_MAX;
    if (B > B_MAX) B = B_MAX;
    if (E > E_MAX) E = E_MAX;

    int nbdr = (KG + 7) / 8;
    int nbsl = (B + 7) / 8;

    cudaStream_t s2;
    cudaEvent_t ev1, ev2;
    cudaStreamCreateWithFlags(&s2, cudaStreamNonBlocking);
    cudaEventCreateWithFlags(&ev1, cudaEventDisableTiming);
    cudaEventCreateWithFlags(&ev2, cudaEventDisableTiming);

    k_prep<<<1, 256>>>(bids, W, bias, wa, B);
    cudaEventRecord(ev1, 0);
    cudaStreamWaitEvent(s2, ev1, 0);

    // stream B: CSR chain (atomic/latency-bound)
    k_hist<<<(E + 255) / 256, 256, 0, s2>>>(ei, E);
    k_scan<<<1, 1024, 0, s2>>>(B);
    k_scatter<<<(E + 255) / 256, 256, 0, s2>>>(ei, E);
    cudaEventRecord(ev2, s2);

    // stream A (default): BW-bound embedding pass, concurrent with CSR chain
    k_fused<<<nbdr + nbsl, 256>>>(ent, bids, KG, B, nbdr);

    cudaStreamWaitEvent(0, ev2, 0);
    k_agg<<<(B + 7) / 8, 256>>>(ei, E, B);
    k_gemm<<<(B + 127) / 128, 256>>>(bias, pw, (float*)d_out, B);

    cudaEventDestroy(ev1);
    cudaEventDestroy(ev2);
    cudaStreamDestroy(s2);
}

// round 9
// speedup vs baseline: 1.2954x; 1.2954x over previous
#include <cuda_runtime.h>
#include <cuda_fp16.h>
#include <stdint.h>

#define KG_MAX 200000
#define B_MAX  20000
#define E_MAX  640000
#define IN_DIM 256
#define OUT_DIM 128

// ---------------- device scratch ----------------
__device__ int   g_is64;
__device__ __align__(16) float g_vL[IN_DIM];
__device__ __align__(16) float g_vR[IN_DIM];
__device__ float g_cLR;
__device__ float g_dR[KG_MAX];
__device__ float g_sL[B_MAX];
__device__ int   g_cnt[B_MAX];
__device__ int   g_cur[B_MAX];
__device__ int   g_off[B_MAX + 1];
__device__ int   g_csr[E_MAX];
__device__ __align__(16) __half g_enth[(size_t)KG_MAX * IN_DIM];
__device__ __align__(16) __half g_Yh[(size_t)B_MAX * IN_DIM];
__device__ __align__(16) unsigned g_Wfrag[16 * 16 * 32 * 2];

__device__ __forceinline__ int ld_row(const void* p, int e, int is64) {
    return is64 ? (int)((const long long*)p)[e] : ((const int*)p)[e];
}
__device__ __forceinline__ int ld_col(const void* p, int E, int e, int is64) {
    return is64 ? (int)((const long long*)p)[(long long)E + e]
                : ((const int*)p)[E + e];
}

// L2 eviction policies via createpolicy + cache_hint (v4-legal on sm_103)
__device__ __forceinline__ unsigned long long pol_keep() {
    unsigned long long p;
    asm("createpolicy.fractional.L2::evict_last.b64 %0, 1.0;" : "=l"(p));
    return p;
}
__device__ __forceinline__ unsigned long long pol_stream() {
    unsigned long long p;
    asm("createpolicy.fractional.L2::evict_first.b64 %0, 1.0;" : "=l"(p));
    return p;
}
__device__ __forceinline__ uint4 ldg_keep(const uint4* p, unsigned long long pol) {
    uint4 q;
    asm volatile("ld.global.nc.L2::cache_hint.v4.u32 {%0,%1,%2,%3}, [%4], %5;"
                 : "=r"(q.x), "=r"(q.y), "=r"(q.z), "=r"(q.w)
                 : "l"(p), "l"(pol));
    return q;
}
__device__ __forceinline__ float4 ldg_stream(const float4* p, unsigned long long pol) {
    float4 q;
    asm volatile("ld.global.nc.L2::cache_hint.v4.f32 {%0,%1,%2,%3}, [%4], %5;"
                 : "=f"(q.x), "=f"(q.y), "=f"(q.z), "=f"(q.w)
                 : "l"(p), "l"(pol));
    return q;
}

// ---------------- k_prep ----------------
__global__ void k_prep(const void* __restrict__ bids,
                       const float* __restrict__ W,
                       const float* __restrict__ bias,
                       const float* __restrict__ wa,
                       int B) {
    int t = threadIdx.x;  // 256
    __shared__ int s_nz;
    if (t == 0) s_nz = 0;
    __syncthreads();
    const unsigned int* u = (const unsigned int*)bids;
    if (u[2 * t + 1] != 0u) atomicOr(&s_nz, 1);
    __syncthreads();
    if (t == 0) g_is64 = s_nz ? 0 : 1;

    float vl = 0.f, vr = 0.f;
#pragma unroll 4
    for (int n = 0; n < OUT_DIM; n++) {
        float w = W[n * IN_DIM + t];
        vl = fmaf(w, wa[n], vl);
        vr = fmaf(w, wa[OUT_DIM + n], vr);
    }
    g_vL[t] = vl;
    g_vR[t] = vr;

    __shared__ float sr[256];
    sr[t] = (t < OUT_DIM) ? bias[t] * (wa[t] + wa[t + OUT_DIM]) : 0.f;
    __syncthreads();
    for (int off = 128; off > 0; off >>= 1) {
        if (t < off) sr[t] += sr[t + off];
        __syncthreads();
    }
    if (t == 0) g_cLR = sr[0];

    // pack W into mma.m16n8k16 B-fragment order (fp16)
    for (int f = t; f < 16 * 16 * 32 * 2; f += 256) {
        int q = f & 1;
        int lane = (f >> 1) & 31;
        int nf = (f >> 6) & 15;
        int ks = f >> 10;
        int n = nf * 8 + (lane >> 2);
        int k = ks * 16 + (lane & 3) * 2 + (q ? 8 : 0);
        __half2 h = __floats2half2_rn(W[n * IN_DIM + k], W[n * IN_DIM + k + 1]);
        g_Wfrag[f] = *(unsigned*)&h;
    }
    for (int i = t; i < B; i += 256) { g_cnt[i] = 0; g_cur[i] = 0; }
}

// ---------------- k_fused: dR + fp16 convert + sL (stream A) --------
__global__ void __launch_bounds__(256) k_fused(
        const float* __restrict__ ent, const void* __restrict__ bids,
        int KG, int B, int nbdr) {
    int bid = blockIdx.x;
    int t = threadIdx.x, w = t >> 5, lane = t & 31;
    if (bid < nbdr) {
        int v = bid * 8 + w;
        if (v < KG) {
            unsigned long long ps = pol_stream();
            const float* x = ent + (size_t)v * IN_DIM + lane * 8;
            float4 x0 = ldg_stream((const float4*)x, ps);
            float4 x1 = ldg_stream((const float4*)(x + 4), ps);
            float4 r0 = *(const float4*)&g_vR[lane * 8];
            float4 r1 = *(const float4*)&g_vR[lane * 8 + 4];
            float d = x0.x * r0.x + x0.y * r0.y + x0.z * r0.z + x0.w * r0.w
                    + x1.x * r1.x + x1.y * r1.y + x1.z * r1.z + x1.w * r1.w;
#pragma unroll
            for (int o = 16; o > 0; o >>= 1)
                d += __shfl_xor_sync(0xffffffffu, d, o);
            if (lane == 0) g_dR[v] = d;
            __half2 h0 = __floats2half2_rn(x0.x, x0.y);
            __half2 h1 = __floats2half2_rn(x0.z, x0.w);
            __half2 h2 = __floats2half2_rn(x1.x, x1.y);
            __half2 h3 = __floats2half2_rn(x1.z, x1.w);
            uint4 q;
            q.x = *(unsigned int*)&h0; q.y = *(unsigned int*)&h1;
            q.z = *(unsigned int*)&h2; q.w = *(unsigned int*)&h3;
            ((uint4*)g_enth)[(size_t)v * 32 + lane] = q;
        }
    } else {
        int r = (bid - nbdr) * 8 + w;
        if (r < B) {
            long long gi = g_is64 ? ((const long long*)bids)[r]
                                  : (long long)((const int*)bids)[r];
            const float* x = ent + gi * (long long)IN_DIM + lane * 8;
            float4 x0 = *(const float4*)x;
            float4 x1 = *(const float4*)(x + 4);
            float4 l0 = *(const float4*)&g_vL[lane * 8];
            float4 l1 = *(const float4*)&g_vL[lane * 8 + 4];
            float d = x0.x * l0.x + x0.y * l0.y + x0.z * l0.z + x0.w * l0.w
                    + x1.x * l1.x + x1.y * l1.y + x1.z * l1.z + x1.w * l1.w;
#pragma unroll
            for (int o = 16; o > 0; o >>= 1)
                d += __shfl_xor_sync(0xffffffffu, d, o);
            if (lane == 0) g_sL[r] = d + g_cLR;
        }
    }
}

// ---------------- CSR chain (stream B) ----------------
__global__ void k_hist(const void* __restrict__ ei, int E) {
    int e = blockIdx.x * blockDim.x + threadIdx.x;
    if (e >= E) return;
    int r = ld_row(ei, e, g_is64);
    atomicAdd(&g_cnt[r], 1);
}

__global__ void k_scan(int B) {
    __shared__ int s[1024];
    int t = threadIdx.x;
    int CH = (B + 1023) >> 10;
    int lo = t * CH, hi = min(lo + CH, B);
    int sum = 0;
    for (int i = lo; i < hi; i++) sum += g_cnt[i];
    s[t] = sum;
    __syncthreads();
    for (int off = 1; off < 1024; off <<= 1) {
        int v = (t >= off) ? s[t - off] : 0;
        __syncthreads();
        s[t] += v;
        __syncthreads();
    }
    int run = (t == 0) ? 0 : s[t - 1];
    for (int i = lo; i < hi; i++) { g_off[i] = run; run += g_cnt[i]; }
    if (t == 1023) g_off[B] = s[1023];
}

__global__ void k_scatter(const void* __restrict__ ei, int E) {
    int e = blockIdx.x * blockDim.x + threadIdx.x;
    if (e >= E) return;
    int r = ld_row(ei, e, g_is64);
    int pos = atomicAdd(&g_cur[r], 1);
    g_csr[g_off[r] + pos] = e;
}

// ---------------- warp-register bitonic sort of 64 ints (2/lane) -----------
__device__ __forceinline__ void bitonic64(int& v0, int& v1, int lane) {
#pragma unroll
    for (int k = 2; k <= 32; k <<= 1) {
#pragma unroll
        for (int j = k >> 1; j > 0; j >>= 1) {
            bool low = ((lane & j) == 0);
            int x0 = __shfl_xor_sync(0xffffffffu, v0, j);
            bool asc0 = ((lane & k) == 0);
            v0 = (asc0 == low) ? min(v0, x0) : max(v0, x0);
            int x1 = __shfl_xor_sync(0xffffffffu, v1, j);
            bool asc1 = (k == 32) ? false : asc0;
            v1 = (asc1 == low) ? min(v1, x1) : max(v1, x1);
        }
    }
    { int mn = min(v0, v1), mx = max(v0, v1); v0 = mn; v1 = mx; }
#pragma unroll
    for (int j = 16; j > 0; j >>= 1) {
        bool low = ((lane & j) == 0);
        int x0 = __shfl_xor_sync(0xffffffffu, v0, j);
        v0 = low ? min(v0, x0) : max(v0, x0);
        int x1 = __shfl_xor_sync(0xffffffffu, v1, j);
        v1 = low ? min(v1, x1) : max(v1, x1);
    }
}

// ---------------- k_agg (R6 structure + evict_last policy gathers) ---------
__global__ void __launch_bounds__(256) k_agg(const void* __restrict__ ei,
                                             int E, int B) {
    __shared__ int   s_e[8][128];
    __shared__ float s_a[8][128];
    int t = threadIdx.x, w = t >> 5, lane = t & 31;
    int r = blockIdx.x * 8 + w;
    if (r >= B) return;
    int is64 = g_is64;
    int off0 = g_off[r];
    int deg = g_off[r + 1] - off0;
    float base = g_sL[r];
    unsigned long long pk = pol_keep();

    const uint4* eh = (const uint4*)g_enth;
    float4 A0 = make_float4(0.f, 0.f, 0.f, 0.f);
    float4 A1 = make_float4(0.f, 0.f, 0.f, 0.f);
    float asum = 0.f;

#define ACC(q, a) do { \
        float2 f0 = __half22float2(*(__half2*)&(q).x); \
        float2 f1 = __half22float2(*(__half2*)&(q).y); \
        float2 f2 = __half22float2(*(__half2*)&(q).z); \
        float2 f3 = __half22float2(*(__half2*)&(q).w); \
        A0.x = fmaf((a), f0.x, A0.x); A0.y = fmaf((a), f0.y, A0.y); \
        A0.z = fmaf((a), f1.x, A0.z); A0.w = fmaf((a), f1.y, A0.w); \
        A1.x = fmaf((a), f2.x, A1.x); A1.y = fmaf((a), f2.y, A1.y); \
        A1.z = fmaf((a), f3.x, A1.z); A1.w = fmaf((a), f3.y, A1.w); \
    } while (0)

#define GATHER_LOOP() do { \
        int i = 0; \
        for (; i + 4 <= deg; i += 4) { \
            int c0 = s_e[w][i],     c1 = s_e[w][i + 1]; \
            int c2 = s_e[w][i + 2], c3 = s_e[w][i + 3]; \
            uint4 q0 = ldg_keep(&eh[(size_t)c0 * 32 + lane], pk); \
            uint4 q1 = ldg_keep(&eh[(size_t)c1 * 32 + lane], pk); \
            uint4 q2 = ldg_keep(&eh[(size_t)c2 * 32 + lane], pk); \
            uint4 q3 = ldg_keep(&eh[(size_t)c3 * 32 + lane], pk); \
            float a0 = s_a[w][i],     a1 = s_a[w][i + 1]; \
            float a2 = s_a[w][i + 2], a3 = s_a[w][i + 3]; \
            ACC(q0, a0); ACC(q1, a1); ACC(q2, a2); ACC(q3, a3); \
        } \
        for (; i < deg; i++) { \
            int c = s_e[w][i]; \
            float a = s_a[w][i]; \
            uint4 q = ldg_keep(&eh[(size_t)c * 32 + lane], pk); \
            ACC(q, a); \
        } \
    } while (0)

    if (deg <= 64) {
        int v0 = (lane < deg) ? g_csr[off0 + lane] : 0x7fffffff;
        int v1 = (32 + lane < deg) ? g_csr[off0 + 32 + lane] : 0x7fffffff;
        bitonic64(v0, v1, lane);
        float ap = 0.f;
        if (lane < deg) {
            int c = ld_col(ei, E, v0, is64);
            float s = base + g_dR[c];
            float v = s >= 0.f ? s : 0.2f * s;
            float a = __expf(-v);
            s_e[w][lane] = c; s_a[w][lane] = a;
            ap += a;
        }
        if (32 + lane < deg) {
            int c = ld_col(ei, E, v1, is64);
            float s = base + g_dR[c];
            float v = s >= 0.f ? s : 0.2f * s;
            float a = __expf(-v);
            s_e[w][32 + lane] = c; s_a[w][32 + lane] = a;
            ap += a;
        }
#pragma unroll
        for (int o = 16; o > 0; o >>= 1)
            ap += __shfl_xor_sync(0xffffffffu, ap, o);
        asum = ap;
        __syncwarp();
        GATHER_LOOP();
    } else if (deg <= 128) {
        int P = 1;
        while (P < deg) P <<= 1;
        for (int i = lane; i < P; i += 32)
            s_e[w][i] = (i < deg) ? g_csr[off0 + i] : 0x7fffffff;
        __syncwarp();
        for (int k = 2; k <= P; k <<= 1) {
            for (int j = k >> 1; j > 0; j >>= 1) {
                for (int i = lane; i < P; i += 32) {
                    int ixj = i ^ j;
                    if (ixj > i) {
                        int a = s_e[w][i], c = s_e[w][ixj];
                        bool up = ((i & k) == 0);
                        if ((a > c) == up) { s_e[w][i] = c; s_e[w][ixj] = a; }
                    }
                }
                __syncwarp();
            }
        }
        float ap = 0.f;
        for (int i = lane; i < deg; i += 32) {
            int e = s_e[w][i];
            int c = ld_col(ei, E, e, is64);
            float s = base + g_dR[c];
            float v = s >= 0.f ? s : 0.2f * s;
            float a = __expf(-v);
            s_e[w][i] = c;
            s_a[w][i] = a;
            ap += a;
        }
#pragma unroll
        for (int o = 16; o > 0; o >>= 1)
            ap += __shfl_xor_sync(0xffffffffu, ap, o);
        asum = ap;
        __syncwarp();
        GATHER_LOOP();
    } else {
        // deterministic fallback: increasing edge-id selection (rare)
        int last = -1;
        for (int rk = 0; rk < deg; rk++) {
            int m = 0x7fffffff;
            for (int i = lane; i < deg; i += 32) {
                int ec = g_csr[off0 + i];
                if (ec > last && ec < m) m = ec;
            }
#pragma unroll
            for (int o = 16; o > 0; o >>= 1)
                m = min(m, __shfl_xor_sync(0xffffffffu, m, o));
            int c = ld_col(ei, E, m, is64);
            float s = base + g_dR[c];
            float v = s >= 0.f ? s : 0.2f * s;
            float a = __expf(-v);
            uint4 q = ldg_keep(&eh[(size_t)c * 32 + lane], pk);
            asum += a;
            ACC(q, a);
            last = m;
        }
    }
#undef GATHER_LOOP
#undef ACC

    float inv = 1.0f / asum;
    __half2 h0 = __floats2half2_rn(A0.x * inv, A0.y * inv);
    __half2 h1 = __floats2half2_rn(A0.z * inv, A0.w * inv);
    __half2 h2 = __floats2half2_rn(A1.x * inv, A1.y * inv);
    __half2 h3 = __floats2half2_rn(A1.z * inv, A1.w * inv);
    uint4 q;
    q.x = *(unsigned*)&h0; q.y = *(unsigned*)&h1;
    q.z = *(unsigned*)&h2; q.w = *(unsigned*)&h3;
    ((uint4*)g_Yh)[(size_t)r * 32 + lane] = q;
}

// ---------------- k_gemm: HMMA m16n8k16 ----------------
__global__ void __launch_bounds__(256) k_gemm(const float* __restrict__ bias,
                                              const float* __restrict__ prelu,
                                              float* __restrict__ out, int M) {
    int tid = threadIdx.x;
    int wid = tid >> 5, lane = tid & 31;
    int gid = lane >> 2, tig = lane & 3;
    int mbase = blockIdx.x * 128 + wid * 16;
    int r0 = mbase + gid, r1 = r0 + 8;
    bool p0 = r0 < M, p1 = r1 < M;

    float acc[16][4];
#pragma unroll
    for (int nf = 0; nf < 16; nf++)
#pragma unroll
        for (int j = 0; j < 4; j++) acc[nf][j] = 0.f;

    const __half* Yh = g_Yh;
    const uint2* Wf = (const uint2*)g_Wfrag;

    for (int ks = 0; ks < 16; ks++) {
        int k0 = ks * 16 + tig * 2;
        unsigned a0 = p0 ? *(const unsigned*)&Yh[(size_t)r0 * IN_DIM + k0] : 0u;
        unsigned a1 = p1 ? *(const unsigned*)&Yh[(size_t)r1 * IN_DIM + k0] : 0u;
        unsigned a2 = p0 ? *(const unsigned*)&Yh[(size_t)r0 * IN_DIM + k0 + 8] : 0u;
        unsigned a3 = p1 ? *(const unsigned*)&Yh[(size_t)r1 * IN_DIM + k0 + 8] : 0u;
#pragma unroll
        for (int nf = 0; nf < 16; nf++) {
            uint2 bb = __ldg(&Wf[(ks * 16 + nf) * 32 + lane]);
            asm volatile(
                "mma.sync.aligned.m16n8k16.row.col.f32.f16.f16.f32 "
                "{%0,%1,%2,%3}, {%4,%5,%6,%7}, {%8,%9}, {%0,%1,%2,%3};"
                : "+f"(acc[nf][0]), "+f"(acc[nf][1]),
                  "+f"(acc[nf][2]), "+f"(acc[nf][3])
                : "r"(a0), "r"(a1), "r"(a2), "r"(a3),
                  "r"(bb.x), "r"(bb.y));
        }
    }

    float pw = prelu[0];
#pragma unroll
    for (int nf = 0; nf < 16; nf++) {
        int n0 = nf * 8 + tig * 2;
        float bv0 = __ldg(&bias[n0]), bv1 = __ldg(&bias[n0 + 1]);
        if (p0) {
            float v0 = acc[nf][0] + bv0, v1 = acc[nf][1] + bv1;
            float2 o;
            o.x = v0 >= 0.f ? v0 : pw * v0;
            o.y = v1 >= 0.f ? v1 : pw * v1;
            *(float2*)&out[(size_t)r0 * OUT_DIM + n0] = o;
        }
        if (p1) {
            float v2 = acc[nf][2] + bv0, v3 = acc[nf][3] + bv1;
            float2 o;
            o.x = v2 >= 0.f ? v2 : pw * v2;
            o.y = v3 >= 0.f ? v3 : pw * v3;
            *(float2*)&out[(size_t)r1 * OUT_DIM + n0] = o;
        }
    }
}

// ---------------- launch ----------------
extern "C" void kernel_launch(void* const* d_in, const int* in_sizes, int n_in,
                              void* d_out, int out_size) {
    const float* ent  = (const float*)d_in[0];
    const void*  bids = d_in[1];
    const void*  ei   = d_in[2];
    const float* W    = (const float*)d_in[3];
    const float* bias = (const float*)d_in[4];
    const float* wa   = (const float*)d_in[5];
    const float* pw   = (const float*)d_in[6];

    int KG = in_sizes[0] / IN_DIM;
    int B  = in_sizes[1];
    int E  = in_sizes[2] / 2;
    if (KG > KG_MAX) KG = KG_MAX;
    if (B > B_MAX) B = B_MAX;
    if (E > E_MAX) E = E_MAX;

    int nbdr = (KG + 7) / 8;
    int nbsl = (B + 7) / 8;

    cudaStream_t s2;
    cudaEvent_t ev1, ev2;
    cudaStreamCreateWithFlags(&s2, cudaStreamNonBlocking);
    cudaEventCreateWithFlags(&ev1, cudaEventDisableTiming);
    cudaEventCreateWithFlags(&ev2, cudaEventDisableTiming);

    k_prep<<<1, 256>>>(bids, W, bias, wa, B);
    cudaEventRecord(ev1, 0);
    cudaStreamWaitEvent(s2, ev1, 0);

    // stream B: CSR chain (atomic/latency-bound)
    k_hist<<<(E + 255) / 256, 256, 0, s2>>>(ei, E);
    k_scan<<<1, 1024, 0, s2>>>(B);
    k_scatter<<<(E + 255) / 256, 256, 0, s2>>>(ei, E);
    cudaEventRecord(ev2, s2);

    // stream A (default): BW-bound embedding pass, concurrent with CSR chain
    k_fused<<<nbdr + nbsl, 256>>>(ent, bids, KG, B, nbdr);

    cudaStreamWaitEvent(0, ev2, 0);
    k_agg<<<(B + 7) / 8, 256>>>(ei, E, B);
    k_gemm<<<(B + 127) / 128, 256>>>(bias, pw, (float*)d_out, B);

    cudaEventDestroy(ev1);
    cudaEventDestroy(ev2);
    cudaStreamDestroy(s2);
}